// round 4
// baseline (speedup 1.0000x reference)
#include <cuda_runtime.h>
#include <math.h>
#include <stdint.h>

// Problem dims (fixed by the dataset)
#define Bz   8
#define Nz   256
#define Dz   512
#define Hz   16
#define Kz   4
#define DKz  32
#define FFNz 2048
#define Mrows 2048            // B*N
#define NEGV (-1e12f)

// -------------------- scratch (no allocations allowed) --------------------
__device__ __align__(16) float g_q   [Bz*Hz*Nz*DKz];
__device__ __align__(16) float g_k   [Bz*Hz*Nz*DKz];
__device__ __align__(16) float g_v   [Bz*Hz*Nz*DKz];
__device__ __align__(16) float g_msgT[Bz*Kz*Hz*DKz*Nz];   // [B][K][H][dk][N], flat == W1 GEMM A
__device__ __align__(16) float g_s1  [Mrows*Dz];
__device__ __align__(16) float g_h   [Mrows*Dz];
__device__ __align__(16) float g_y   [Mrows*Dz];
__device__ __align__(16) float g_f1  [Mrows*FFNz];
__device__ __align__(16) float g_f2  [Mrows*Dz];

// -------------------- f32x2 packed-FMA helpers (Blackwell baseline ISA) ---
__device__ __forceinline__ unsigned long long fma2(unsigned long long a,
                                                   unsigned long long b,
                                                   unsigned long long c) {
    unsigned long long d;
    asm("fma.rn.f32x2 %0, %1, %2, %3;" : "=l"(d) : "l"(a), "l"(b), "l"(c));
    return d;
}
__device__ __forceinline__ unsigned long long packff(float x, float y) {
    unsigned long long d;
    asm("mov.b64 %0, {%1, %2};" : "=l"(d) : "r"(__float_as_uint(x)), "r"(__float_as_uint(y)));
    return d;
}

// ==================== SGEMM v3: fp32 packed-FMA (f32x2) ====================
// C[M,N] = A[M,K] @ W[K,N] + bias (+epilogue), all fp32.
// CTA tile 128(M) x 64(N), BK=16, 256 threads, microtile 8(M) x 4(N).
// Accumulators are f32x2 pairs ALONG M: the A operand is a natural 8-byte
// broadcast LDS; only B needs mov.b64 packing (4 per k per thread).
// EPI: 0 bias, 1 silu, 2 exact gelu, 3 bias + scatter to [B,H,N,dk]
template<int EPI>
__global__ __launch_bounds__(256)
void sgemm2(const float* __restrict__ A, const float* __restrict__ W,
            const float* __restrict__ bias, float* __restrict__ C,
            int M, int N, int K)
{
    __shared__ float As[16][136];   // [k][m], stride 136 floats: 16B-aligned rows,
                                    // k-vs-k+8 staging stores land on distinct banks
    __shared__ float Bs[16][68];    // [k][n]

    const int tid = threadIdx.x;
    const int n0  = blockIdx.x * 64;
    const int m0  = blockIdx.y * 128;

    // staging map
    const int a_row = tid & 127;          // 0..127
    const int a_k   = (tid >> 7) * 8;     // 0 or 8
    const int b_k   = tid >> 4;           // 0..15
    const int b_n   = (tid & 15) * 4;

    const float* Ap = A + (size_t)(m0 + a_row) * K + a_k;
    const float* Bp = W + (size_t)b_k * N + n0 + b_n;

    // compute map
    const int tn = (tid & 15) * 4;        // col offset in tile
    const int tm = (tid >> 4) * 8;        // row offset in tile

    unsigned long long acc[4][4];
#pragma unroll
    for (int i = 0; i < 4; i++)
#pragma unroll
        for (int j = 0; j < 4; j++) acc[i][j] = 0ULL;

    const int S = K >> 4;

    // prefetch stage 0
    float4 ra0 = *(const float4*)(Ap);
    float4 ra1 = *(const float4*)(Ap + 4);
    float4 rb  = *(const float4*)(Bp);

    for (int s = 0; s < S; s++) {
        // write staged regs to smem
        As[a_k + 0][a_row] = ra0.x;
        As[a_k + 1][a_row] = ra0.y;
        As[a_k + 2][a_row] = ra0.z;
        As[a_k + 3][a_row] = ra0.w;
        As[a_k + 4][a_row] = ra1.x;
        As[a_k + 5][a_row] = ra1.y;
        As[a_k + 6][a_row] = ra1.z;
        As[a_k + 7][a_row] = ra1.w;
        *(float4*)&Bs[b_k][b_n] = rb;
        __syncthreads();

        // prefetch next stage (latency overlapped with compute below)
        if (s + 1 < S) {
            Ap += 16;
            Bp += (size_t)16 * N;
            ra0 = *(const float4*)(Ap);
            ra1 = *(const float4*)(Ap + 4);
            rb  = *(const float4*)(Bp);
        }

#pragma unroll
        for (int k = 0; k < 16; k++) {
            // A: 2x LDS.128 broadcast -> 4 m-pairs as u64
            const ulonglong2 a01 = *(const ulonglong2*)&As[k][tm];
            const ulonglong2 a23 = *(const ulonglong2*)&As[k][tm + 4];
            const float4 b = *(const float4*)&Bs[k][tn];
            unsigned long long bb[4];
            bb[0] = packff(b.x, b.x);
            bb[1] = packff(b.y, b.y);
            bb[2] = packff(b.z, b.z);
            bb[3] = packff(b.w, b.w);
            const unsigned long long a2[4] = {a01.x, a01.y, a23.x, a23.y};
#pragma unroll
            for (int i = 0; i < 4; i++)
#pragma unroll
                for (int j = 0; j < 4; j++)
                    acc[i][j] = fma2(a2[i], bb[j], acc[i][j]);
        }
        __syncthreads();
    }

    // -------- epilogue --------
    const float4 bv = *(const float4*)&bias[n0 + tn];
    const float bias4[4] = {bv.x, bv.y, bv.z, bv.w};

    float vals[8][4];
#pragma unroll
    for (int i = 0; i < 4; i++) {
#pragma unroll
        for (int j = 0; j < 4; j++) {
            float lo = __uint_as_float((uint32_t)(acc[i][j] & 0xffffffffULL));
            float hi = __uint_as_float((uint32_t)(acc[i][j] >> 32));
            lo += bias4[j]; hi += bias4[j];
            if (EPI == 1) {
                lo = lo / (1.f + expf(-lo));
                hi = hi / (1.f + expf(-hi));
            } else if (EPI == 2) {
                lo = 0.5f * lo * (1.f + erff(lo * 0.70710678118654752f));
                hi = 0.5f * hi * (1.f + erff(hi * 0.70710678118654752f));
            }
            vals[2 * i][j]     = lo;
            vals[2 * i + 1][j] = hi;
        }
    }

#pragma unroll
    for (int rr = 0; rr < 8; rr++) {
        const int r = m0 + tm + rr;
        float* dst;
        if (EPI == 3) {
            const int b = r >> 8, n = r & 255, h = (n0 + tn) >> 5, d = (n0 + tn) & 31;
            dst = C + (((size_t)(b * Hz + h) * Nz + n) * DKz) + d;
        } else {
            dst = C + (size_t)r * N + n0 + tn;
        }
        *(float4*)dst = make_float4(vals[rr][0], vals[rr][1], vals[rr][2], vals[rr][3]);
    }
}

// -------------------- attention v2 (unchanged from R2) --------------------
__global__ __launch_bounds__(256, 2)
void attn_kernel(const float* __restrict__ q, const float* __restrict__ k,
                 const float* __restrict__ v, const float* __restrict__ dist,
                 const float* __restrict__ dbar, const float* __restrict__ bias,
                 const int* __restrict__ mask, float* __restrict__ msgT)
{
    extern __shared__ float sh[];
    float* ks  = sh;                    // 256*33
    float* vsT = sh + 256 * 33;         // 32*260
    float* P   = vsT + 32 * 260;        // 32*260

    const int bh   = blockIdx.x;
    const int b    = bh >> 4;
    const int h    = bh & 15;
    const int n0   = blockIdx.y * 32;
    const int tid  = threadIdx.x;
    const int lane = tid & 31;
    const int wid  = tid >> 5;
    const int tx   = tid & 15;
    const int ty   = tid >> 4;

    const float* kb = k + (size_t)bh * (Nz * DKz);
    const float* vb = v + (size_t)bh * (Nz * DKz);
    for (int i = tid; i < Nz * DKz; i += 256) {
        const int m = i >> 5, d = i & 31;
        ks[m * 33 + d]   = kb[i];
        vsT[d * 260 + m] = vb[i];
    }
    __syncthreads();

    float dbv[4];
#pragma unroll
    for (int kk = 0; kk < 4; kk++) dbv[kk] = dbar[kk];

    float s[4][8], nd[4][8];
#pragma unroll
    for (int r = 0; r < 4; r++) {
        const int n = n0 + wid * 4 + r;
        const float* qrow = q + ((size_t)bh * Nz + n) * DKz;
        float qr[32];
        const float4* q4 = (const float4*)qrow;
#pragma unroll
        for (int d4 = 0; d4 < 8; d4++) {
            float4 t = q4[d4];
            qr[d4 * 4 + 0] = t.x * 0.17677669529663687f;
            qr[d4 * 4 + 1] = t.y * 0.17677669529663687f;
            qr[d4 * 4 + 2] = t.z * 0.17677669529663687f;
            qr[d4 * 4 + 3] = t.w * 0.17677669529663687f;
        }
        const int*   mrow = mask + ((size_t)b * Nz + n) * Nz;
        const float* drow = dist + (size_t)b * 255 * 255 + (size_t)(n - 1) * 255 - 1;
#pragma unroll
        for (int j = 0; j < 8; j++) {
            const int m = j * 32 + lane;
            float acc = 0.f;
#pragma unroll
            for (int d = 0; d < 32; d++) acc = fmaf(qr[d], ks[m * 33 + d], acc);
            s[r][j] = acc;
            float ndv;
            if (n == 0 || m == 0) ndv = -1.f;
            else                  ndv = drow[m];
            if (mrow[m] == 0)     ndv = 1e30f;
            nd[r][j] = ndv;
        }
    }

    const int r0 = ty, r1 = ty + 16;
    const int d0 = tx, d1 = tx + 16;
    const float4* pr0 = (const float4*)(P + r0 * 260);
    const float4* pr1 = (const float4*)(P + r1 * 260);
    const float4* vd0 = (const float4*)(vsT + d0 * 260);
    const float4* vd1 = (const float4*)(vsT + d1 * 260);

    for (int kk = 0; kk < 4; kk++) {
        const float db = dbv[kk];
#pragma unroll
        for (int r = 0; r < 4; r++) {
            const int n = n0 + wid * 4 + r;
            const float* brow = bias + (((size_t)(b * Kz + kk) * Nz + n) * Nz);
            float e[8];
            float mx = -INFINITY;
#pragma unroll
            for (int j = 0; j < 8; j++) {
                const int m = j * 32 + lane;
                const float sc = (nd[r][j] < db) ? s[r][j] + brow[m] : NEGV;
                e[j] = sc;
                mx = fmaxf(mx, sc);
            }
#pragma unroll
            for (int o = 16; o > 0; o >>= 1)
                mx = fmaxf(mx, __shfl_xor_sync(0xffffffffu, mx, o));
            float sum = 0.f;
#pragma unroll
            for (int j = 0; j < 8; j++) {
                e[j] = expf(e[j] - mx);
                sum += e[j];
            }
#pragma unroll
            for (int o = 16; o > 0; o >>= 1)
                sum += __shfl_xor_sync(0xffffffffu, sum, o);
            const float inv = 1.f / sum;
#pragma unroll
            for (int j = 0; j < 8; j++)
                P[(wid * 4 + r) * 260 + j * 32 + lane] = e[j] * inv;
        }
        __syncthreads();

        float a00 = 0.f, a01 = 0.f, a10 = 0.f, a11 = 0.f;
#pragma unroll 4
        for (int mc = 0; mc < 64; mc++) {
            const float4 p0 = pr0[mc];
            const float4 p1 = pr1[mc];
            const float4 w0 = vd0[mc];
            const float4 w1 = vd1[mc];
            a00 = fmaf(p0.x, w0.x, a00); a00 = fmaf(p0.y, w0.y, a00);
            a00 = fmaf(p0.z, w0.z, a00); a00 = fmaf(p0.w, w0.w, a00);
            a01 = fmaf(p0.x, w1.x, a01); a01 = fmaf(p0.y, w1.y, a01);
            a01 = fmaf(p0.z, w1.z, a01); a01 = fmaf(p0.w, w1.w, a01);
            a10 = fmaf(p1.x, w0.x, a10); a10 = fmaf(p1.y, w0.y, a10);
            a10 = fmaf(p1.z, w0.z, a10); a10 = fmaf(p1.w, w0.w, a10);
            a11 = fmaf(p1.x, w1.x, a11); a11 = fmaf(p1.y, w1.y, a11);
            a11 = fmaf(p1.z, w1.z, a11); a11 = fmaf(p1.w, w1.w, a11);
        }

        float* ob = msgT + ((((size_t)(b * Kz + kk) * Hz + h) * DKz)) * Nz;
        ob[(size_t)d0 * Nz + n0 + r0] = a00;
        ob[(size_t)d1 * Nz + n0 + r0] = a01;
        ob[(size_t)d0 * Nz + n0 + r1] = a10;
        ob[(size_t)d1 * Nz + n0 + r1] = a11;
        __syncthreads();
    }
}

// -------------------- residual + layernorm --------------------
__global__ __launch_bounds__(128)
void ln_kernel(const float* __restrict__ hbuf, const float* __restrict__ res,
               const float* __restrict__ g, const float* __restrict__ be,
               float* __restrict__ out)
{
    __shared__ float red[4];
    const int row = blockIdx.x;
    const int tid = threadIdx.x;
    const float* hp = hbuf + (size_t)row * Dz;
    const float* rp = res  + (size_t)row * Dz;

    float vv[4];
    float sum = 0.f;
#pragma unroll
    for (int i = 0; i < 4; i++) {
        vv[i] = hp[i * 128 + tid] + rp[i * 128 + tid];
        sum += vv[i];
    }
#pragma unroll
    for (int o = 16; o > 0; o >>= 1) sum += __shfl_xor_sync(0xffffffffu, sum, o);
    if ((tid & 31) == 0) red[tid >> 5] = sum;
    __syncthreads();
    const float mean = (red[0] + red[1] + red[2] + red[3]) * (1.f / 512.f);

    float var = 0.f;
#pragma unroll
    for (int i = 0; i < 4; i++) { const float t = vv[i] - mean; var += t * t; }
#pragma unroll
    for (int o = 16; o > 0; o >>= 1) var += __shfl_xor_sync(0xffffffffu, var, o);
    __syncthreads();
    if ((tid & 31) == 0) red[tid >> 5] = var;
    __syncthreads();
    var = (red[0] + red[1] + red[2] + red[3]) * (1.f / 512.f);
    const float rstd = rsqrtf(var + 1e-6f);

#pragma unroll
    for (int i = 0; i < 4; i++) {
        const int c = i * 128 + tid;
        out[(size_t)row * Dz + c] = (vv[i] - mean) * rstd * g[c] + be[c];
    }
}

// -------------------- launcher --------------------
extern "C" void kernel_launch(void* const* d_in, const int* in_sizes, int n_in,
                              void* d_out, int out_size)
{
    const float* x    = (const float*)d_in[0];
    const float* dist = (const float*)d_in[1];
    const float* dbar = (const float*)d_in[2];
    const float* bias = (const float*)d_in[3];
    const int*   mask = (const int*)d_in[4];
    const int off = (in_sizes[5] == 1) ? 6 : 5;
    const float* Wq  = (const float*)d_in[off + 0];
    const float* bq  = (const float*)d_in[off + 1];
    const float* Wk  = (const float*)d_in[off + 2];
    const float* bk  = (const float*)d_in[off + 3];
    const float* Wv  = (const float*)d_in[off + 4];
    const float* bv  = (const float*)d_in[off + 5];
    const float* W1  = (const float*)d_in[off + 6];
    const float* b1  = (const float*)d_in[off + 7];
    const float* W2  = (const float*)d_in[off + 8];
    const float* b2  = (const float*)d_in[off + 9];
    const float* g1  = (const float*)d_in[off + 10];
    const float* be1 = (const float*)d_in[off + 11];
    const float* Wf1 = (const float*)d_in[off + 12];
    const float* bf1 = (const float*)d_in[off + 13];
    const float* Wf2 = (const float*)d_in[off + 14];
    const float* bf2 = (const float*)d_in[off + 15];
    const float* g2  = (const float*)d_in[off + 16];
    const float* be2 = (const float*)d_in[off + 17];
    float* out = (float*)d_out;

    float *q, *k, *v, *msgT, *s1, *hh, *y, *f1, *f2;
    cudaGetSymbolAddress((void**)&q,    g_q);
    cudaGetSymbolAddress((void**)&k,    g_k);
    cudaGetSymbolAddress((void**)&v,    g_v);
    cudaGetSymbolAddress((void**)&msgT, g_msgT);
    cudaGetSymbolAddress((void**)&s1,   g_s1);
    cudaGetSymbolAddress((void**)&hh,   g_h);
    cudaGetSymbolAddress((void**)&y,    g_y);
    cudaGetSymbolAddress((void**)&f1,   g_f1);
    cudaGetSymbolAddress((void**)&f2,   g_f2);

    const int ATTN_SMEM = (256 * 33 + 32 * 260 + 32 * 260) * (int)sizeof(float);
    cudaFuncSetAttribute(attn_kernel, cudaFuncAttributeMaxDynamicSharedMemorySize, ATTN_SMEM);

    // 1) QKV projections -> [B,H,N,dk]  (packed-FMA GEMM, scatter epilogue)
    {
        dim3 grid(Dz / 64, Mrows / 128);
        sgemm2<3><<<grid, 256>>>(x, Wq, bq, q, Mrows, Dz, Dz);
        sgemm2<3><<<grid, 256>>>(x, Wk, bk, k, Mrows, Dz, Dz);
        sgemm2<3><<<grid, 256>>>(x, Wv, bv, v, Mrows, Dz, Dz);
    }

    // 2) multi-scale masked attention -> msgT [B,K,H,dk,N]
    {
        dim3 grid(Bz * Hz, Nz / 32);
        attn_kernel<<<grid, 256, ATTN_SMEM>>>(q, k, v, dist, dbar, bias, mask, msgT);
    }

    // 3) silu(msgT @ W1 + b1) -> s1
    sgemm2<1><<<dim3(Dz / 64, Mrows / 128), 256>>>(msgT, W1, b1, s1, Mrows, Dz, Kz * Dz);

    // 4) s1 @ W2 + b2 -> h
    sgemm2<0><<<dim3(Dz / 64, Mrows / 128), 256>>>(s1, W2, b2, hh, Mrows, Dz, Dz);

    // 5) y = LN(h + x)
    ln_kernel<<<Mrows, 128>>>(hh, x, g1, be1, y);

    // 6) gelu(y @ Wf1 + bf1) -> f1
    sgemm2<2><<<dim3(FFNz / 64, Mrows / 128), 256>>>(y, Wf1, bf1, f1, Mrows, FFNz, Dz);

    // 7) f1 @ Wf2 + bf2 -> f2
    sgemm2<0><<<dim3(Dz / 64, Mrows / 128), 256>>>(f1, Wf2, bf2, f2, Mrows, Dz, FFNz);

    // 8) out = LN(f2 + y)
    ln_kernel<<<Mrows, 128>>>(f2, y, g2, be2, out);
}